// round 2
// baseline (speedup 1.0000x reference)
#include <cuda_runtime.h>
#include <cstdint>

// Problem constants
#define BSZ 8
#define HH  64
#define WW  64
#define CC  512
#define NP  (HH*WW)    // 4096 query positions
#define MP  (NP/4)     // 1024 pooled key positions
#define CE  (CC/8)     // 64  qk dim
#define CD  (CC/2)     // 256 v dim

// Scratch (static device globals — allocation-free)
__device__ float g_buf [BSZ*NP*CE];            // 8.4 MB
__device__ float xf_buf[BSZ*NP*CE];            // 8.4 MB
__device__ float xh_buf[BSZ*NP*CD];            // 33.5 MB
__device__ float f_buf [BSZ*MP*CE];            // 2.1 MB
__device__ float h_buf [BSZ*MP*CD];            // 8.4 MB
__device__ float s_buf [(size_t)BSZ*NP*MP];    // 134 MB
__device__ float o_buf [BSZ*NP*CD];            // 33.5 MB

// ---------------------------------------------------------------------------
// Generic tiled NN GEMM: C[M,N] = A[M,K] * B[K,N], all row-major.
// BM=BN=64, BK=16, 256 threads, 4x4 micro-tile per thread.
// Optional epilogue: C = gamma[0]*acc + resid  (for final residual add).
// Batched via blockIdx.z with element strides sA/sB/sC.
// Requires M%64==0, N%64==0, K%16==0 (all shapes here satisfy this).
// ---------------------------------------------------------------------------
__global__ void gemm_nn_kernel(const float* __restrict__ A,
                               const float* __restrict__ B,
                               float*       __restrict__ C,
                               int M, int N, int K,
                               long long sA, long long sB, long long sC,
                               const float* __restrict__ gamma,
                               const float* __restrict__ resid)
{
    __shared__ float As[16][64];
    __shared__ float Bs[16][64];

    const int b = blockIdx.z;
    A += (size_t)b * sA;
    B += (size_t)b * sB;
    C += (size_t)b * sC;

    const int tid     = threadIdx.x;
    const int tm      = (tid / 16) * 4;
    const int tn      = (tid % 16) * 4;
    const int rowBase = blockIdx.y * 64;
    const int colBase = blockIdx.x * 64;

    float acc[4][4] = {};

    for (int k0 = 0; k0 < K; k0 += 16) {
        // A tile 64x16 -> As[k][m] (transposed). One float4 per thread.
        {
            int m   = tid >> 2;           // 0..63
            int kk4 = (tid & 3) * 4;      // 0,4,8,12
            float4 a4 = *(const float4*)&A[(size_t)(rowBase + m) * K + k0 + kk4];
            As[kk4 + 0][m] = a4.x;
            As[kk4 + 1][m] = a4.y;
            As[kk4 + 2][m] = a4.z;
            As[kk4 + 3][m] = a4.w;
        }
        // B tile 16x64 -> Bs[k][n]. One float4 per thread.
        {
            int kk = tid >> 4;            // 0..15
            int n4 = (tid & 15) * 4;      // 0..60
            float4 b4 = *(const float4*)&B[(size_t)(k0 + kk) * N + colBase + n4];
            *(float4*)&Bs[kk][n4] = b4;
        }
        __syncthreads();

        #pragma unroll
        for (int kk = 0; kk < 16; kk++) {
            float4 a4 = *(const float4*)&As[kk][tm];
            float4 b4 = *(const float4*)&Bs[kk][tn];
            float av[4] = {a4.x, a4.y, a4.z, a4.w};
            float bv[4] = {b4.x, b4.y, b4.z, b4.w};
            #pragma unroll
            for (int i = 0; i < 4; i++)
                #pragma unroll
                for (int j = 0; j < 4; j++)
                    acc[i][j] = fmaf(av[i], bv[j], acc[i][j]);
        }
        __syncthreads();
    }

    const float gval = gamma ? gamma[0] : 0.0f;
    #pragma unroll
    for (int i = 0; i < 4; i++) {
        int row = rowBase + tm + i;
        #pragma unroll
        for (int j = 0; j < 4; j++) {
            int col = colBase + tn + j;
            size_t idx = (size_t)row * N + col;
            float v = acc[i][j];
            if (gamma) v = fmaf(gval, v, resid[idx]);
            C[idx] = v;
        }
    }
}

// ---------------------------------------------------------------------------
// Tiled NT GEMM: C[M,N] = A[M,K] * B[N,K]^T (both row-major, K contiguous).
// Used for S = G @ F^T per batch (M=4096, N=1024, K=64).
// ---------------------------------------------------------------------------
__global__ void gemm_nt_kernel(const float* __restrict__ A,
                               const float* __restrict__ B,
                               float*       __restrict__ C,
                               int M, int N, int K,
                               long long sA, long long sB, long long sC)
{
    __shared__ float As[16][64];
    __shared__ float Bs[16][64];

    const int b = blockIdx.z;
    A += (size_t)b * sA;
    B += (size_t)b * sB;
    C += (size_t)b * sC;

    const int tid     = threadIdx.x;
    const int tm      = (tid / 16) * 4;
    const int tn      = (tid % 16) * 4;
    const int rowBase = blockIdx.y * 64;
    const int colBase = blockIdx.x * 64;

    float acc[4][4] = {};

    for (int k0 = 0; k0 < K; k0 += 16) {
        {
            int m   = tid >> 2;
            int kk4 = (tid & 3) * 4;
            float4 a4 = *(const float4*)&A[(size_t)(rowBase + m) * K + k0 + kk4];
            As[kk4 + 0][m] = a4.x;
            As[kk4 + 1][m] = a4.y;
            As[kk4 + 2][m] = a4.z;
            As[kk4 + 3][m] = a4.w;
        }
        {
            int n   = tid >> 2;
            int kk4 = (tid & 3) * 4;
            float4 b4 = *(const float4*)&B[(size_t)(colBase + n) * K + k0 + kk4];
            Bs[kk4 + 0][n] = b4.x;
            Bs[kk4 + 1][n] = b4.y;
            Bs[kk4 + 2][n] = b4.z;
            Bs[kk4 + 3][n] = b4.w;
        }
        __syncthreads();

        #pragma unroll
        for (int kk = 0; kk < 16; kk++) {
            float4 a4 = *(const float4*)&As[kk][tm];
            float4 b4 = *(const float4*)&Bs[kk][tn];
            float av[4] = {a4.x, a4.y, a4.z, a4.w};
            float bv[4] = {b4.x, b4.y, b4.z, b4.w};
            #pragma unroll
            for (int i = 0; i < 4; i++)
                #pragma unroll
                for (int j = 0; j < 4; j++)
                    acc[i][j] = fmaf(av[i], bv[j], acc[i][j]);
        }
        __syncthreads();
    }

    #pragma unroll
    for (int i = 0; i < 4; i++) {
        int row = rowBase + tm + i;
        #pragma unroll
        for (int j = 0; j < 4; j++) {
            int col = colBase + tn + j;
            C[(size_t)row * N + col] = acc[i][j];
        }
    }
}

// ---------------------------------------------------------------------------
// 2x2 max pool, stride 2, NHWC (64x64 -> 32x32), channel count Cch.
// ---------------------------------------------------------------------------
__global__ void pool_kernel(const float* __restrict__ in,
                            float* __restrict__ out, int Cch)
{
    int idx = blockIdx.x * blockDim.x + threadIdx.x;
    int total = BSZ * 32 * 32 * Cch;
    if (idx >= total) return;
    int c = idx % Cch;
    int q = (idx / Cch) % 32;
    int p = (idx / (Cch * 32)) % 32;
    int b = idx / (Cch * 32 * 32);
    const float* base = in + (size_t)b * NP * Cch;
    size_t i00 = ((size_t)(2 * p) * 64 + 2 * q) * Cch + c;
    float v = base[i00];
    v = fmaxf(v, base[i00 + Cch]);
    v = fmaxf(v, base[i00 + (size_t)64 * Cch]);
    v = fmaxf(v, base[i00 + (size_t)64 * Cch + Cch]);
    out[idx] = v;
}

// ---------------------------------------------------------------------------
// Row softmax over 1024 columns, in-place. One block (256 thr) per row.
// ---------------------------------------------------------------------------
__global__ void softmax_kernel(float* __restrict__ S)
{
    __shared__ float redmax[8];
    __shared__ float redsum[8];

    float* r = S + (size_t)blockIdx.x * MP;
    int t = threadIdx.x;

    float4 v = ((float4*)r)[t];
    float m = fmaxf(fmaxf(v.x, v.y), fmaxf(v.z, v.w));
    #pragma unroll
    for (int o = 16; o > 0; o >>= 1)
        m = fmaxf(m, __shfl_xor_sync(0xffffffffu, m, o));
    if ((t & 31) == 0) redmax[t >> 5] = m;
    __syncthreads();
    m = redmax[0];
    #pragma unroll
    for (int i = 1; i < 8; i++) m = fmaxf(m, redmax[i]);

    float e0 = __expf(v.x - m);
    float e1 = __expf(v.y - m);
    float e2 = __expf(v.z - m);
    float e3 = __expf(v.w - m);
    float s = e0 + e1 + e2 + e3;
    #pragma unroll
    for (int o = 16; o > 0; o >>= 1)
        s += __shfl_xor_sync(0xffffffffu, s, o);
    if ((t & 31) == 0) redsum[t >> 5] = s;
    __syncthreads();
    s = 0.0f;
    #pragma unroll
    for (int i = 0; i < 8; i++) s += redsum[i];

    float inv = 1.0f / s;
    float4 o4 = make_float4(e0 * inv, e1 * inv, e2 * inv, e3 * inv);
    ((float4*)r)[t] = o4;
}

// ---------------------------------------------------------------------------
// Launch
// ---------------------------------------------------------------------------
extern "C" void kernel_launch(void* const* d_in, const int* in_sizes, int n_in,
                              void* d_out, int out_size)
{
    const float* x     = (const float*)d_in[0];
    const float* Wf    = (const float*)d_in[1];
    const float* Wg    = (const float*)d_in[2];
    const float* Wh    = (const float*)d_in[3];
    const float* Wo    = (const float*)d_in[4];
    const float* gamma = (const float*)d_in[5];
    float* out = (float*)d_out;

    float *g_p, *xf_p, *xh_p, *f_p, *h_p, *s_p, *o_p;
    cudaGetSymbolAddress((void**)&g_p,  g_buf);
    cudaGetSymbolAddress((void**)&xf_p, xf_buf);
    cudaGetSymbolAddress((void**)&xh_p, xh_buf);
    cudaGetSymbolAddress((void**)&f_p,  f_buf);
    cudaGetSymbolAddress((void**)&h_p,  h_buf);
    cudaGetSymbolAddress((void**)&s_p,  s_buf);
    cudaGetSymbolAddress((void**)&o_p,  o_buf);

    const int MROWS = BSZ * NP;  // 32768

    // Projections: g = X@Wg, xf = X@Wf, xh = X@Wh
    gemm_nn_kernel<<<dim3(CE / 64, MROWS / 64, 1), 256>>>(
        x, Wg, g_p, MROWS, CE, CC, 0, 0, 0, nullptr, nullptr);
    gemm_nn_kernel<<<dim3(CE / 64, MROWS / 64, 1), 256>>>(
        x, Wf, xf_p, MROWS, CE, CC, 0, 0, 0, nullptr, nullptr);
    gemm_nn_kernel<<<dim3(CD / 64, MROWS / 64, 1), 256>>>(
        x, Wh, xh_p, MROWS, CD, CC, 0, 0, 0, nullptr, nullptr);

    // 2x2 max pools
    pool_kernel<<<(BSZ * 32 * 32 * CE + 255) / 256, 256>>>(xf_p, f_p, CE);
    pool_kernel<<<(BSZ * 32 * 32 * CD + 255) / 256, 256>>>(xh_p, h_p, CD);

    // S = G @ F^T  (per batch)
    gemm_nt_kernel<<<dim3(MP / 64, NP / 64, BSZ), 256>>>(
        g_p, f_p, s_p, NP, MP, CE,
        (long long)NP * CE, (long long)MP * CE, (long long)NP * MP);

    // softmax over keys (rows of length 1024)
    softmax_kernel<<<BSZ * NP, 256>>>(s_p);

    // O = P @ H  (per batch)
    gemm_nn_kernel<<<dim3(CD / 64, NP / 64, BSZ), 256>>>(
        s_p, h_p, o_p, NP, CD, MP,
        (long long)NP * MP, (long long)MP * CD, (long long)NP * CD, nullptr, nullptr);

    // out = gamma * (O @ Wo) + x
    gemm_nn_kernel<<<dim3(CC / 64, MROWS / 64, 1), 256>>>(
        o_p, Wo, out, MROWS, CC, CD, 0, 0, 0, gamma, x);
}

// round 4
// speedup vs baseline: 2.2613x; 2.2613x over previous
#include <cuda_runtime.h>
#include <cstdint>

#define BSZ 8
#define NP  4096
#define MP  1024
#define CCH 512
#define CE  64
#define CD  256
#define NCAT 384

// ---------------- scratch (static device globals) ----------------
__device__ float wcat_buf[NCAT * CCH];              // [384,512] = [Wg|Wf|Wh]^T
__device__ float wot_buf [CCH * CD];                // [512,256] = Wo^T
__device__ float gfh_buf [(size_t)BSZ * NP * NCAT]; // [B*4096, 384]
__device__ float f_buf   [BSZ * MP * CE];           // [B,1024,64]
__device__ float ht_buf  [BSZ * CD * MP];           // [B,256,1024]
__device__ float s_buf   [(size_t)BSZ * NP * MP];   // [B,4096,1024]
__device__ float o_buf   [(size_t)BSZ * NP * CD];   // [B,4096,256]

__device__ __forceinline__ uint32_t f2tf32(float f) {
    uint32_t r;
    asm("cvt.rna.tf32.f32 %0, %1;" : "=r"(r) : "f"(f));
    return r;
}

__device__ __forceinline__ void mma_tf32(float c[4], const uint32_t a[4], const uint32_t b[2]) {
    asm volatile(
        "mma.sync.aligned.m16n8k8.row.col.f32.tf32.tf32.f32 "
        "{%0,%1,%2,%3}, {%4,%5,%6,%7}, {%8,%9}, {%0,%1,%2,%3};"
        : "+f"(c[0]), "+f"(c[1]), "+f"(c[2]), "+f"(c[3])
        : "r"(a[0]), "r"(a[1]), "r"(a[2]), "r"(a[3]), "r"(b[0]), "r"(b[1]));
}

// ---------------------------------------------------------------------------
// Warp-tiled tf32 mma GEMM: C[M,N] = A[M,K] * B[N,K]^T (both K-major).
// CTA tile 128x128, K-chunk 32. 8 warps: 4(m) x 2(n), warp tile 32m x 64n.
// EPI=1: C = gamma[0]*acc + resid. Requires M%128==0, N%128==0, K%32==0.
// Batched via blockIdx.z strides.
// ---------------------------------------------------------------------------
template <int EPI>
__global__ void __launch_bounds__(256) mma_gemm(
    const float* __restrict__ A, const float* __restrict__ B, float* __restrict__ C,
    int K, int lda, int ldb, int ldc,
    long long strA, long long strB, long long strC,
    const float* __restrict__ gamma, const float* __restrict__ resid)
{
    __shared__ uint32_t As[32][133];   // [k][m], pad 133: conflict-free STS, <=2-way LDS
    __shared__ uint32_t Bs[32][133];   // [k][n]

    const int tid  = threadIdx.x;
    const int wid  = tid >> 5;
    const int lane = tid & 31;
    const int bz   = blockIdx.z;
    A += (size_t)bz * strA;
    B += (size_t)bz * strB;
    C += (size_t)bz * strC;
    const int rowBase = blockIdx.y * 128;
    const int colBase = blockIdx.x * 128;

    const int wm = (wid >> 1) * 32;   // 0,32,64,96
    const int wn = (wid & 1) * 64;    // 0,64
    const int grp   = lane >> 2;      // 0..7
    const int quad  = lane & 3;       // 0..3

    float acc[2][8][4] = {};

    for (int k0 = 0; k0 < K; k0 += 32) {
        // A tile 128x32 -> As[k][m]  (1024 float4 slots, 4 per thread)
        #pragma unroll
        for (int i = 0; i < 4; i++) {
            int idx = tid + 256 * i;
            int r = idx >> 3, c4 = (idx & 7) * 4;
            float4 v = *(const float4*)(A + (size_t)(rowBase + r) * lda + k0 + c4);
            As[c4 + 0][r] = f2tf32(v.x);
            As[c4 + 1][r] = f2tf32(v.y);
            As[c4 + 2][r] = f2tf32(v.z);
            As[c4 + 3][r] = f2tf32(v.w);
        }
        // B tile 128x32 -> Bs[k][n]
        #pragma unroll
        for (int i = 0; i < 4; i++) {
            int idx = tid + 256 * i;
            int r = idx >> 3, c4 = (idx & 7) * 4;
            float4 v = *(const float4*)(B + (size_t)(colBase + r) * ldb + k0 + c4);
            Bs[c4 + 0][r] = f2tf32(v.x);
            Bs[c4 + 1][r] = f2tf32(v.y);
            Bs[c4 + 2][r] = f2tf32(v.z);
            Bs[c4 + 3][r] = f2tf32(v.w);
        }
        __syncthreads();

        #pragma unroll
        for (int s = 0; s < 4; s++) {
            const int kk = s * 8;
            uint32_t af[2][4];
            uint32_t bf[8][2];
            #pragma unroll
            for (int mi = 0; mi < 2; mi++) {
                af[mi][0] = As[kk + quad    ][wm + mi * 16 + grp];
                af[mi][1] = As[kk + quad    ][wm + mi * 16 + 8 + grp];
                af[mi][2] = As[kk + 4 + quad][wm + mi * 16 + grp];
                af[mi][3] = As[kk + 4 + quad][wm + mi * 16 + 8 + grp];
            }
            #pragma unroll
            for (int ni = 0; ni < 8; ni++) {
                bf[ni][0] = Bs[kk + quad    ][wn + ni * 8 + grp];
                bf[ni][1] = Bs[kk + 4 + quad][wn + ni * 8 + grp];
            }
            #pragma unroll
            for (int mi = 0; mi < 2; mi++)
                #pragma unroll
                for (int ni = 0; ni < 8; ni++)
                    mma_tf32(acc[mi][ni], af[mi], bf[ni]);
        }
        __syncthreads();
    }

    // epilogue
    const float gval = EPI ? gamma[0] : 0.0f;
    #pragma unroll
    for (int mi = 0; mi < 2; mi++) {
        #pragma unroll
        for (int half = 0; half < 2; half++) {
            const int row = rowBase + wm + mi * 16 + half * 8 + grp;
            float* cp = C + (size_t)row * ldc + colBase + wn + quad * 2;
            #pragma unroll
            for (int ni = 0; ni < 8; ni++) {
                float v0 = acc[mi][ni][half * 2 + 0];
                float v1 = acc[mi][ni][half * 2 + 1];
                if (EPI) {
                    const float* rp = resid + (size_t)row * ldc + colBase + wn + quad * 2 + ni * 8;
                    float2 rv = *(const float2*)rp;
                    v0 = fmaf(gval, v0, rv.x);
                    v1 = fmaf(gval, v1, rv.y);
                }
                *(float2*)(cp + ni * 8) = make_float2(v0, v1);
            }
        }
    }
}

// ---------------------------------------------------------------------------
// weight prep: wcat[n][k] = [Wg|Wf|Wh](k, n'),  wot[n][k] = Wo[k][n]
// ---------------------------------------------------------------------------
__global__ void prep_weights(const float* __restrict__ Wf, const float* __restrict__ Wg,
                             const float* __restrict__ Wh, const float* __restrict__ Wo,
                             float* __restrict__ wcat, float* __restrict__ wot)
{
    int idx = blockIdx.x * 256 + threadIdx.x;
    if (idx < NCAT * CCH) {
        int n = idx / CCH, k = idx % CCH;
        float v;
        if (n < 64)       v = Wg[(size_t)k * 64 + n];
        else if (n < 128) v = Wf[(size_t)k * 64 + (n - 64)];
        else              v = Wh[(size_t)k * 256 + (n - 128)];
        wcat[idx] = v;
    }
    if (idx < CCH * CD) {
        int n = idx / CD, k = idx % CD;
        wot[idx] = Wo[(size_t)k * CCH + n];
    }
}

// ---------------------------------------------------------------------------
// pools: f from gfh cols [64,128); ht (transposed) from cols [128,384)
// ---------------------------------------------------------------------------
__global__ void pool_f(const float* __restrict__ gfh, float* __restrict__ f)
{
    int idx = blockIdx.x * 256 + threadIdx.x;
    if (idx >= BSZ * MP * CE) return;
    int e = idx & 63;
    int m = (idx >> 6) & 1023;
    int b = idx >> 16;
    int p = m >> 5, q = m & 31;
    const float* base = gfh + ((size_t)b * NP + 2 * p * 64 + 2 * q) * NCAT + 64 + e;
    f[idx] = fmaxf(fmaxf(base[0], base[NCAT]),
                   fmaxf(base[64 * NCAT], base[64 * NCAT + NCAT]));
}

__global__ void pool_ht(const float* __restrict__ gfh, float* __restrict__ ht)
{
    int idx = blockIdx.x * 256 + threadIdx.x;
    if (idx >= BSZ * CD * MP) return;
    int m = idx & 1023;
    int c = (idx >> 10) & 255;
    int b = idx >> 18;
    int p = m >> 5, q = m & 31;
    const float* base = gfh + ((size_t)b * NP + 2 * p * 64 + 2 * q) * NCAT + 128 + c;
    ht[idx] = fmaxf(fmaxf(base[0], base[NCAT]),
                    fmaxf(base[64 * NCAT], base[64 * NCAT + NCAT]));
}

// ---------------------------------------------------------------------------
// row softmax over 1024 cols, in-place; one 256-thread block per row
// ---------------------------------------------------------------------------
__global__ void softmax_kernel(float* __restrict__ S)
{
    __shared__ float redmax[8];
    __shared__ float redsum[8];
    float* r = S + (size_t)blockIdx.x * MP;
    int t = threadIdx.x;

    float4 v = ((float4*)r)[t];
    float m = fmaxf(fmaxf(v.x, v.y), fmaxf(v.z, v.w));
    #pragma unroll
    for (int o = 16; o > 0; o >>= 1) m = fmaxf(m, __shfl_xor_sync(0xffffffffu, m, o));
    if ((t & 31) == 0) redmax[t >> 5] = m;
    __syncthreads();
    m = redmax[0];
    #pragma unroll
    for (int i = 1; i < 8; i++) m = fmaxf(m, redmax[i]);

    float e0 = __expf(v.x - m), e1 = __expf(v.y - m);
    float e2 = __expf(v.z - m), e3 = __expf(v.w - m);
    float s = e0 + e1 + e2 + e3;
    #pragma unroll
    for (int o = 16; o > 0; o >>= 1) s += __shfl_xor_sync(0xffffffffu, s, o);
    if ((t & 31) == 0) redsum[t >> 5] = s;
    __syncthreads();
    s = 0.0f;
    #pragma unroll
    for (int i = 0; i < 8; i++) s += redsum[i];

    float inv = 1.0f / s;
    ((float4*)r)[t] = make_float4(e0 * inv, e1 * inv, e2 * inv, e3 * inv);
}

// ---------------------------------------------------------------------------
// launch
// ---------------------------------------------------------------------------
extern "C" void kernel_launch(void* const* d_in, const int* in_sizes, int n_in,
                              void* d_out, int out_size)
{
    const float* x     = (const float*)d_in[0];
    const float* Wf    = (const float*)d_in[1];
    const float* Wg    = (const float*)d_in[2];
    const float* Wh    = (const float*)d_in[3];
    const float* Wo    = (const float*)d_in[4];
    const float* gamma = (const float*)d_in[5];
    float* out = (float*)d_out;

    float *wcat_p, *wot_p, *gfh_p, *f_p, *ht_p, *s_p, *o_p;
    cudaGetSymbolAddress((void**)&wcat_p, wcat_buf);
    cudaGetSymbolAddress((void**)&wot_p,  wot_buf);
    cudaGetSymbolAddress((void**)&gfh_p,  gfh_buf);
    cudaGetSymbolAddress((void**)&f_p,    f_buf);
    cudaGetSymbolAddress((void**)&ht_p,   ht_buf);
    cudaGetSymbolAddress((void**)&s_p,    s_buf);
    cudaGetSymbolAddress((void**)&o_p,    o_buf);

    // weight transpose/concat
    prep_weights<<<(NCAT * CCH + 255) / 256, 256>>>(Wf, Wg, Wh, Wo, wcat_p, wot_p);

    // fused projections: gfh[32768,384] = X[32768,512] @ wcat^T
    mma_gemm<0><<<dim3(3, 256, 1), 256>>>(
        x, wcat_p, gfh_p, CCH, CCH, CCH, NCAT, 0, 0, 0, nullptr, nullptr);

    // pools
    pool_f <<<(BSZ * MP * CE + 255) / 256, 256>>>(gfh_p, f_p);
    pool_ht<<<(BSZ * CD * MP + 255) / 256, 256>>>(gfh_p, ht_p);

    // S[b] = G[b] @ F[b]^T   (M=4096, N=1024, K=64)
    mma_gemm<0><<<dim3(8, 32, BSZ), 256>>>(
        gfh_p, f_p, s_p, CE, NCAT, CE, MP,
        (long long)NP * NCAT, (long long)MP * CE, (long long)NP * MP, nullptr, nullptr);

    // softmax over keys
    softmax_kernel<<<BSZ * NP, 256>>>(s_p);

    // O[b] = P[b] @ Ht[b]^T  (M=4096, N=256, K=1024)
    mma_gemm<0><<<dim3(2, 32, BSZ), 256>>>(
        s_p, ht_p, o_p, MP, MP, MP, CD,
        (long long)NP * MP, (long long)CD * MP, (long long)NP * CD, nullptr, nullptr);

    // out = gamma * (O @ Wo^T_prepped) + x   (M=32768, N=512, K=256)
    mma_gemm<1><<<dim3(4, 256, 1), 256>>>(
        o_p, wot_p, out, CD, CD, CD, CCH, 0, 0, 0, gamma, x);
}